// round 1
// baseline (speedup 1.0000x reference)
#include <cuda_runtime.h>
#include <cstdint>

#define NVEC     131072      // 32 * 64 * 64 vectors
#define DDIM     128
#define KCODES   1024
#define BN       64          // vectors per block
#define BKC      256         // codes per chunk
#define CSTR     257         // padded row stride for code tile (conflict-free)
#define NTHREADS 256

#define SMEM_BYTES ((DDIM * BN + DDIM * CSTR + BN) * 4)

__device__ int   g_idx[NVEC];
__device__ float g_snorm[KCODES];

// ||c_k||^2, sequential fp32 mul+add (no contraction) to mirror the reference's
// elementwise square -> sum pipeline.
__global__ void snorm_kernel(const float* __restrict__ cb) {
    int k = blockIdx.x * blockDim.x + threadIdx.x;
    if (k >= KCODES) return;
    const float* row = cb + k * DDIM;
    float s = 0.f;
#pragma unroll 1
    for (int i = 0; i < DDIM; i++) {
        s = __fadd_rn(s, __fmul_rn(row[i], row[i]));
    }
    g_snorm[k] = s;
}

// For each of BN vectors, compute argmin_k fl( fl(r + s_k) - 2*p_k ) with
// lowest-index tie-break, replicating the reference's fp32 quantization.
__global__ void __launch_bounds__(NTHREADS, 1)
argmin_kernel(const float* __restrict__ z, const float* __restrict__ cb) {
    extern __shared__ float smem[];
    float* zs = smem;                 // [128][64]   z tile, transposed (d-major)
    float* cs = smem + DDIM * BN;     // [128][257]  code tile, padded
    float* rs = cs + DDIM * CSTR;     // [64]        ||z||^2 per vector

    const int nbase = blockIdx.x * BN;
    const int b  = nbase >> 12;          // n = b*4096 + h*64 + w
    const int hw = nbase & 4095;
    const float* zb = z + (size_t)b * (DDIM * 4096) + hw;

    // Load z tile: global coalesced over hw, smem write conflict-free.
    for (int t = threadIdx.x; t < DDIM * BN; t += NTHREADS) {
        int i = t >> 6, nl = t & (BN - 1);
        zs[i * BN + nl] = zb[(size_t)i * 4096 + nl];
    }
    __syncthreads();

    // r_n = sequential fp32 sum of squares over d (i = 0..127 in order).
    if (threadIdx.x < BN) {
        float r = 0.f;
#pragma unroll 1
        for (int i = 0; i < DDIM; i++) {
            float v = zs[i * BN + threadIdx.x];
            r = __fadd_rn(r, __fmul_rn(v, v));
        }
        rs[threadIdx.x] = r;
    }
    __syncthreads();

    const int tn = threadIdx.x >> 5;   // warp id: owns vectors tn*8..tn*8+7
    const int tk = threadIdx.x & 31;   // lane: owns codes tk + 32*j

    float rreg[8];
#pragma unroll
    for (int n = 0; n < 8; n++) rreg[n] = rs[tn * 8 + n];

    float best[8];
    int   bidx[8];
#pragma unroll
    for (int n = 0; n < 8; n++) { best[n] = 3.4e38f; bidx[n] = 0; }

    for (int chunk = 0; chunk < KCODES / BKC; chunk++) {
        const int kbase = chunk * BKC;
        __syncthreads();
        // Fill code tile transposed: gmem coalesced over i, smem stride-257 writes.
        for (int t = threadIdx.x; t < BKC * DDIM; t += NTHREADS) {
            int kl = t >> 7, i = t & (DDIM - 1);
            cs[i * CSTR + kl] = cb[(kbase + kl) * DDIM + i];
        }
        __syncthreads();

        float acc[64];
#pragma unroll
        for (int a = 0; a < 64; a++) acc[a] = 0.f;

#pragma unroll 2
        for (int d = 0; d < DDIM; d++) {
            float4 za  = *(const float4*)(zs + d * BN + tn * 8);
            float4 zb4 = *(const float4*)(zs + d * BN + tn * 8 + 4);
            float zv[8] = {za.x, za.y, za.z, za.w, zb4.x, zb4.y, zb4.z, zb4.w};
            float cv[8];
#pragma unroll
            for (int j = 0; j < 8; j++) cv[j] = cs[d * CSTR + tk + j * 32];
#pragma unroll
            for (int n = 0; n < 8; n++)
#pragma unroll
                for (int j = 0; j < 8; j++)
                    acc[n * 8 + j] = __fmaf_rn(zv[n], cv[j], acc[n * 8 + j]);
        }

        // dist = fl( fl(r + s_k) - 2*p ): 2*p is exact in fp32, so the fused
        // FMA's single rounding equals the reference's separate subtract.
#pragma unroll
        for (int j = 0; j < 8; j++) {
            const int k = kbase + tk + j * 32;
            const float s = g_snorm[k];
#pragma unroll
            for (int n = 0; n < 8; n++) {
                float dist = __fmaf_rn(-2.f, acc[n * 8 + j], __fadd_rn(rreg[n], s));
                if (dist < best[n] || (dist == best[n] && k < bidx[n])) {
                    best[n] = dist; bidx[n] = k;
                }
            }
        }
    }

    // Cross-lane argmin per vector, lowest-index tie-break.
#pragma unroll
    for (int n = 0; n < 8; n++) {
        float v = best[n]; int id = bidx[n];
#pragma unroll
        for (int off = 16; off > 0; off >>= 1) {
            float v2 = __shfl_down_sync(0xffffffffu, v, off);
            int   i2 = __shfl_down_sync(0xffffffffu, id, off);
            if (v2 < v || (v2 == v && i2 < id)) { v = v2; id = i2; }
        }
        if (tk == 0) g_idx[nbase + tn * 8 + n] = id;
    }
}

// out[b, i, h, w] = codebook[idx[b, h, w], i] — coalesced writes, L2-resident gathers.
__global__ void gather_kernel(const float* __restrict__ cb, float* __restrict__ out) {
    int o = blockIdx.x * blockDim.x + threadIdx.x;
    int hw = o & 4095;
    int i  = (o >> 12) & (DDIM - 1);
    int b  = o >> 19;
    int n  = (b << 12) | hw;
    out[o] = cb[g_idx[n] * DDIM + i];
}

extern "C" void kernel_launch(void* const* d_in, const int* in_sizes, int n_in,
                              void* d_out, int out_size) {
    const float* z  = (const float*)d_in[0];
    const float* cb = (const float*)d_in[1];
    float* out = (float*)d_out;

    cudaFuncSetAttribute(argmin_kernel,
                         cudaFuncAttributeMaxDynamicSharedMemorySize, SMEM_BYTES);

    snorm_kernel<<<(KCODES + 255) / 256, 256>>>(cb);
    argmin_kernel<<<NVEC / BN, NTHREADS, SMEM_BYTES>>>(z, cb);
    gather_kernel<<<(NVEC * DDIM) / 256, 256>>>(cb, out);
}

// round 2
// speedup vs baseline: 1.0787x; 1.0787x over previous
#include <cuda_runtime.h>
#include <cstdint>

#define NVEC     131072      // 32 * 64 * 64 vectors
#define DDIM     128
#define KCODES   1024
#define BN       64          // vectors per block
#define BKC      256         // codes per chunk
#define CSTR     257         // padded row stride for code tile (conflict-free)
#define NTHREADS 256

#define SMEM_BYTES ((DDIM * BN + DDIM * CSTR + BN) * 4)

typedef unsigned long long u64;

__device__ int   g_idx[NVEC];
__device__ float g_snorm[KCODES];

// ||c_k||^2: float4 loads (width only), strictly sequential i=0..127 fp32
// mul+add — bit-identical to the reference's elementwise square -> sum.
__global__ void snorm_kernel(const float* __restrict__ cb) {
    int k = blockIdx.x * blockDim.x + threadIdx.x;
    if (k >= KCODES) return;
    const float4* row = (const float4*)(cb + k * DDIM);
    float4 v[32];
#pragma unroll
    for (int i = 0; i < 32; i++) v[i] = row[i];
    float s = 0.f;
#pragma unroll
    for (int i = 0; i < 32; i++) {
        s = __fadd_rn(s, __fmul_rn(v[i].x, v[i].x));
        s = __fadd_rn(s, __fmul_rn(v[i].y, v[i].y));
        s = __fadd_rn(s, __fmul_rn(v[i].z, v[i].z));
        s = __fadd_rn(s, __fmul_rn(v[i].w, v[i].w));
    }
    g_snorm[k] = s;
}

// For each of BN vectors: argmin_k fl( fl(r + s_k) - 2*p_k ), lowest-index
// tie-break. Inner product via packed fma.rn.f32x2 — each lane of the pair is
// an IEEE fp32 FMA in the same d-order as the scalar version (bit-identical).
__global__ void __launch_bounds__(NTHREADS, 1)
argmin_kernel(const float* __restrict__ z, const float* __restrict__ cb) {
    extern __shared__ float smem[];
    float* zs = smem;                 // [128][64]   z tile, transposed (d-major)
    float* cs = smem + DDIM * BN;     // [128][257]  code tile, padded
    float* rs = cs + DDIM * CSTR;     // [64]        ||z||^2 per vector

    const int nbase = blockIdx.x * BN;
    const int b  = nbase >> 12;          // n = b*4096 + h*64 + w
    const int hw = nbase & 4095;
    const float* zb = z + (size_t)b * (DDIM * 4096) + hw;

    // Load z tile: global coalesced over hw, smem write conflict-free.
    for (int t = threadIdx.x; t < DDIM * BN; t += NTHREADS) {
        int i = t >> 6, nl = t & (BN - 1);
        zs[i * BN + nl] = zb[(size_t)i * 4096 + nl];
    }
    __syncthreads();

    // r_n = sequential fp32 sum of squares over d (i = 0..127 in order).
    if (threadIdx.x < BN) {
        float r = 0.f;
#pragma unroll 1
        for (int i = 0; i < DDIM; i++) {
            float v = zs[i * BN + threadIdx.x];
            r = __fadd_rn(r, __fmul_rn(v, v));
        }
        rs[threadIdx.x] = r;
    }
    __syncthreads();

    const int tn = threadIdx.x >> 5;   // warp id: owns vectors tn*8..tn*8+7
    const int tk = threadIdx.x & 31;   // lane: owns codes tk + 32*j

    float rreg[8];
#pragma unroll
    for (int n = 0; n < 8; n++) rreg[n] = rs[tn * 8 + n];

    float best[8];
    int   bidx[8];
#pragma unroll
    for (int n = 0; n < 8; n++) { best[n] = 3.4e38f; bidx[n] = 0; }

    for (int chunk = 0; chunk < KCODES / BKC; chunk++) {
        const int kbase = chunk * BKC;
        __syncthreads();
        // Fill code tile transposed: gmem coalesced over i, stride-257 writes.
        for (int t = threadIdx.x; t < BKC * DDIM; t += NTHREADS) {
            int kl = t >> 7, i = t & (DDIM - 1);
            cs[i * CSTR + kl] = cb[(kbase + kl) * DDIM + i];
        }
        __syncthreads();

        // accp[n2*8+j]: lo = acc[2*n2][j], hi = acc[2*n2+1][j]
        u64 accp[32];
#pragma unroll
        for (int a = 0; a < 32; a++) accp[a] = 0ull;

#pragma unroll 2
        for (int d = 0; d < DDIM; d++) {
            const float* zrow = zs + d * BN + tn * 8;
            u64 zp[4];
#pragma unroll
            for (int n2 = 0; n2 < 4; n2++)
                zp[n2] = *(const u64*)(zrow + 2 * n2);   // (z[2n2], z[2n2+1])
            const float* crow = cs + d * CSTR + tk;
#pragma unroll
            for (int j = 0; j < 8; j++) {
                float c = crow[j * 32];
                u64 cd;
                asm("mov.b64 %0, {%1, %1};" : "=l"(cd) : "f"(c));
#pragma unroll
                for (int n2 = 0; n2 < 4; n2++)
                    asm("fma.rn.f32x2 %0, %1, %2, %0;"
                        : "+l"(accp[n2 * 8 + j]) : "l"(zp[n2]), "l"(cd));
            }
        }

        // dist = fl( fl(r + s_k) - 2*p ): 2*p exact in fp32, so the fused
        // FMA's single rounding equals the reference's separate subtract.
#pragma unroll
        for (int j = 0; j < 8; j++) {
            const int k = kbase + tk + j * 32;
            const float s = g_snorm[k];
#pragma unroll
            for (int n2 = 0; n2 < 4; n2++) {
                u64 ap = accp[n2 * 8 + j];
                float plo = __uint_as_float((unsigned)(ap & 0xffffffffu));
                float phi = __uint_as_float((unsigned)(ap >> 32));
                int nlo = 2 * n2, nhi = 2 * n2 + 1;
                float dlo = __fmaf_rn(-2.f, plo, __fadd_rn(rreg[nlo], s));
                float dhi = __fmaf_rn(-2.f, phi, __fadd_rn(rreg[nhi], s));
                if (dlo < best[nlo] || (dlo == best[nlo] && k < bidx[nlo])) {
                    best[nlo] = dlo; bidx[nlo] = k;
                }
                if (dhi < best[nhi] || (dhi == best[nhi] && k < bidx[nhi])) {
                    best[nhi] = dhi; bidx[nhi] = k;
                }
            }
        }
    }

    // Cross-lane argmin per vector, lowest-index tie-break.
#pragma unroll
    for (int n = 0; n < 8; n++) {
        float v = best[n]; int id = bidx[n];
#pragma unroll
        for (int off = 16; off > 0; off >>= 1) {
            float v2 = __shfl_down_sync(0xffffffffu, v, off);
            int   i2 = __shfl_down_sync(0xffffffffu, id, off);
            if (v2 < v || (v2 == v && i2 < id)) { v = v2; id = i2; }
        }
        if (tk == 0) g_idx[nbase + tn * 8 + n] = id;
    }
}

// out[b, i, h, w] = codebook[idx[b, h, w], i] — coalesced writes, L2-resident gathers.
__global__ void gather_kernel(const float* __restrict__ cb, float* __restrict__ out) {
    int o = blockIdx.x * blockDim.x + threadIdx.x;
    int hw = o & 4095;
    int i  = (o >> 12) & (DDIM - 1);
    int b  = o >> 19;
    int n  = (b << 12) | hw;
    out[o] = cb[g_idx[n] * DDIM + i];
}

extern "C" void kernel_launch(void* const* d_in, const int* in_sizes, int n_in,
                              void* d_out, int out_size) {
    const float* z  = (const float*)d_in[0];
    const float* cb = (const float*)d_in[1];
    float* out = (float*)d_out;

    cudaFuncSetAttribute(argmin_kernel,
                         cudaFuncAttributeMaxDynamicSharedMemorySize, SMEM_BYTES);

    snorm_kernel<<<(KCODES + 255) / 256, 256>>>(cb);
    argmin_kernel<<<NVEC / BN, NTHREADS, SMEM_BYTES>>>(z, cb);
    gather_kernel<<<(NVEC * DDIM) / 256, 256>>>(cb, out);
}